// round 10
// baseline (speedup 1.0000x reference)
#include <cuda_runtime.h>
#include <math.h>

// FraudDetectionHybridModel — closed-form quantum-circuit reduction.
// feats(patch) = prefix products of cos(pixel); RZ(patch_params) is pure phase (unused).
// out[b] = sigmoid( cos( sum_{p,w} feats[b,p,w] * W[p*4+w] ) )
//
// R10 = R9 lean body at finer CTA grain:
//  CTA = 128 threads = 4 warps = 2 images; grid = B/2 = 2048 (same 8192 warps,
//  single wave). Warp pair {0,1} owns image 0, {2,3} image 1; 4-warp barrier.

#define NPAIRS_HALF 49

// acc += <prefix-cos-products, (wa,wb)> for the two patches in one item (Horner)
__device__ __forceinline__ float item_contrib(float4 top, float4 bot,
                                              const float* __restrict__ wp,
                                              float acc)
{
    const float cA0 = __cosf(top.x), cA1 = __cosf(top.y);
    const float cA2 = __cosf(bot.x), cA3 = __cosf(bot.y);
    const float cB0 = __cosf(top.z), cB1 = __cosf(top.w);
    const float cB2 = __cosf(bot.z), cB3 = __cosf(bot.w);

    const float4 wa = __ldg(reinterpret_cast<const float4*>(wp));
    const float4 wb = __ldg(reinterpret_cast<const float4*>(wp + 4));

    const float hA = fmaf(cA1, fmaf(cA2, fmaf(cA3, wa.w, wa.z), wa.y), wa.x);
    acc = fmaf(cA0, hA, acc);
    const float hB = fmaf(cB1, fmaf(cB2, fmaf(cB3, wb.w, wb.z), wb.y), wb.x);
    acc = fmaf(cB0, hB, acc);
    return acc;
}

// final cos: Cody-Waite 2-term reduction + __cosf (|a| <~ 200), err ~1e-6
__device__ __forceinline__ float fast_cos_mid(float a)
{
    const float INV_2PI = 0.15915493667125702f;
    const float PI2_HI  = 6.28125f;
    const float PI2_LO  = 1.9353071795864769e-3f;
    const float k = rintf(a * INV_2PI);
    float r = fmaf(-k, PI2_HI, a);
    r = fmaf(-k, PI2_LO, r);
    return __cosf(r);
}

__global__ void __launch_bounds__(128, 16)
fraud_kernel(const float* __restrict__ x,   // [B, 784]
             const float* __restrict__ w,   // [785]
             float* __restrict__ out,       // [B]
             int B)
{
    const int tid  = threadIdx.x;
    const int warp = tid >> 5;                 // 0..3
    const int lane = tid & 31;

    int b = blockIdx.x * 2 + (warp >> 1);
    if (b >= B) b = B - 1;                     // safe duplicate; store guarded
    const int half = warp & 1;

    const float* xb = x + (size_t)b * 784;

    // ---- item 1: p0 in [0,98) ----
    const int p0 = half * NPAIRS_HALF + lane;
    const int i0 = p0 / 7, c0 = p0 - i0 * 7;
    const float* q0 = xb + i0 * 56 + c0 * 4;
    const float4 t0 = __ldg(reinterpret_cast<const float4*>(q0));
    const float4 b0 = __ldg(reinterpret_cast<const float4*>(q0 + 28));

    // ---- item 2: p1 = p0 + 32 (lanes < 17 only) ----
    // weight offset: always +64 floats; pixel offset: +240 if c0<3 else +268
    const bool a1 = (lane < NPAIRS_HALF - 32);
    const float* q1 = q0 + ((c0 < 3) ? 240 : 268);
    float4 t1 = make_float4(0.f, 0.f, 0.f, 0.f), b1 = t1;
    if (a1) {
        t1 = __ldg(reinterpret_cast<const float4*>(q1));
        b1 = __ldg(reinterpret_cast<const float4*>(q1 + 28));
    }

    // ---- compute ----
    const float* wp0 = w + (i0 * 14 + 2 * c0) * 4;
    float acc = item_contrib(t0, b0, wp0, 0.0f);
    if (a1) acc = item_contrib(t1, b1, wp0 + 256, acc);

    // ---- warp butterfly reduce ----
    #pragma unroll
    for (int off = 16; off > 0; off >>= 1)
        acc += __shfl_xor_sync(0xffffffffu, acc, off);

    __shared__ float wsum[4];
    if (lane == 0) wsum[warp] = acc;
    __syncthreads();

    // each even warp finalizes its image — parallel tails
    if (lane == 0 && (warp & 1) == 0) {
        const int img = blockIdx.x * 2 + (warp >> 1);
        if (img < B) {
            const float a  = wsum[warp] + wsum[warp + 1];
            const float cv = fast_cos_mid(a);
            out[img] = 1.0f / (1.0f + __expf(-cv));
        }
    }
}

extern "C" void kernel_launch(void* const* d_in, const int* in_sizes, int n_in,
                              void* d_out, int out_size)
{
    const float* x = (const float*)d_in[0];   // [B,1,28,28]
    // d_in[1] = patch_params — provably unused (RZ is pure phase)
    const float* w = (const float*)d_in[2];   // [785]
    float* out = (float*)d_out;

    const int B = in_sizes[0] / 784;
    const int grid = (B + 1) / 2;
    fraud_kernel<<<grid, 128>>>(x, w, out, B);
}

// round 12
// speedup vs baseline: 1.2905x; 1.2905x over previous
#include <cuda_runtime.h>
#include <math.h>

// FraudDetectionHybridModel — closed-form quantum-circuit reduction.
// feats(patch) = prefix products of cos(pixel); RZ(patch_params) is pure phase (unused).
// out[b] = sigmoid( cos( sum_{p,w} feats[b,p,w] * W[p*4+w] ) )
//
// R12 = R9 (best, 6.656us; block 256, grid B/4, Horner body) with an
// asymmetric barrier tail: odd warps bar.arrive (publish wsum and retire),
// even warps bar.sync then finalize their image. No other changes.

#define NPAIRS_HALF 49

// acc += <prefix-cos-products, (wa,wb)> for the two patches in one item (Horner)
__device__ __forceinline__ float item_contrib(float4 top, float4 bot,
                                              const float* __restrict__ wp,
                                              float acc)
{
    const float cA0 = __cosf(top.x), cA1 = __cosf(top.y);
    const float cA2 = __cosf(bot.x), cA3 = __cosf(bot.y);
    const float cB0 = __cosf(top.z), cB1 = __cosf(top.w);
    const float cB2 = __cosf(bot.z), cB3 = __cosf(bot.w);

    const float4 wa = __ldg(reinterpret_cast<const float4*>(wp));
    const float4 wb = __ldg(reinterpret_cast<const float4*>(wp + 4));

    const float hA = fmaf(cA1, fmaf(cA2, fmaf(cA3, wa.w, wa.z), wa.y), wa.x);
    acc = fmaf(cA0, hA, acc);
    const float hB = fmaf(cB1, fmaf(cB2, fmaf(cB3, wb.w, wb.z), wb.y), wb.x);
    acc = fmaf(cB0, hB, acc);
    return acc;
}

// final cos: Cody-Waite 2-term reduction + __cosf (|a| <~ 200), err ~1e-6
__device__ __forceinline__ float fast_cos_mid(float a)
{
    const float INV_2PI = 0.15915493667125702f;
    const float PI2_HI  = 6.28125f;
    const float PI2_LO  = 1.9353071795864769e-3f;
    const float k = rintf(a * INV_2PI);
    float r = fmaf(-k, PI2_HI, a);
    r = fmaf(-k, PI2_LO, r);
    return __cosf(r);
}

__global__ void __launch_bounds__(256, 8)
fraud_kernel(const float* __restrict__ x,   // [B, 784]
             const float* __restrict__ w,   // [785]
             float* __restrict__ out,       // [B]
             int B)
{
    const int tid  = threadIdx.x;
    const int warp = tid >> 5;
    const int lane = tid & 31;

    int b = blockIdx.x * 4 + (warp >> 1);
    if (b >= B) b = B - 1;                    // safe duplicate work; store is guarded
    const int half = warp & 1;

    const float* xb = x + (size_t)b * 784;

    // ---- item 1: p0 in [0,98) ----
    const int p0 = half * NPAIRS_HALF + lane;
    const int i0 = p0 / 7, c0 = p0 - i0 * 7;
    const float* q0 = xb + i0 * 56 + c0 * 4;
    const float4 t0 = __ldg(reinterpret_cast<const float4*>(q0));
    const float4 b0 = __ldg(reinterpret_cast<const float4*>(q0 + 28));

    // ---- item 2: p1 = p0 + 32 (lanes < 17 only) ----
    // weight offset: always +64 floats; pixel offset: +240 if c0<3 else +268
    const bool a1 = (lane < NPAIRS_HALF - 32);
    const float* q1 = q0 + ((c0 < 3) ? 240 : 268);
    float4 t1 = make_float4(0.f, 0.f, 0.f, 0.f), b1 = t1;
    if (a1) {
        t1 = __ldg(reinterpret_cast<const float4*>(q1));
        b1 = __ldg(reinterpret_cast<const float4*>(q1 + 28));
    }

    // ---- compute ----
    const float* wp0 = w + (i0 * 14 + 2 * c0) * 4;
    float acc = item_contrib(t0, b0, wp0, 0.0f);
    if (a1) acc = item_contrib(t1, b1, wp0 + 256, acc);

    // ---- warp butterfly reduce ----
    #pragma unroll
    for (int off = 16; off > 0; off >>= 1)
        acc += __shfl_xor_sync(0xffffffffu, acc, off);

    __shared__ float wsum[8];
    if (lane == 0) wsum[warp] = acc;

    // asymmetric barrier: odd warps publish + retire; even warps wait + finalize
    if (warp & 1) {
        asm volatile("bar.arrive 1, 256;" ::: "memory");
    } else {
        asm volatile("bar.sync 1, 256;" ::: "memory");
        if (lane == 0) {
            const int img = blockIdx.x * 4 + (warp >> 1);
            if (img < B) {
                const float a  = wsum[warp] + wsum[warp + 1];
                const float cv = fast_cos_mid(a);
                out[img] = 1.0f / (1.0f + __expf(-cv));
            }
        }
    }
}

extern "C" void kernel_launch(void* const* d_in, const int* in_sizes, int n_in,
                              void* d_out, int out_size)
{
    const float* x = (const float*)d_in[0];   // [B,1,28,28]
    // d_in[1] = patch_params — provably unused (RZ is pure phase)
    const float* w = (const float*)d_in[2];   // [785]
    float* out = (float*)d_out;

    const int B = in_sizes[0] / 784;
    const int grid = (B + 3) / 4;
    fraud_kernel<<<grid, 256>>>(x, w, out, B);
}

// round 13
// speedup vs baseline: 1.3029x; 1.0096x over previous
#include <cuda_runtime.h>
#include <math.h>

// FraudDetectionHybridModel — closed-form quantum-circuit reduction. FINAL (R9).
//
// Math: per 2x2 patch with pixels t0..t3 (row-major),
//   feats = [cos t0, cos t0 cos t1, cos t0 cos t1 cos t2, cos t0 cos t1 cos t2 cos t3]
// (RZ(patch_params) is pure phase -> no effect on <Z>; the CNOT chain turns the
//  independent product-state qubits into prefix-XOR parities -> prefix cos products.)
// out[b] = sigmoid( cos( sum_{p,w} feats[b,p,w] * W[p*4+w] ) ),  W = classifier_params[:784].
//
// Structure (best measured config, 6.656us):
//  - block 256 = 8 warps, grid = B/4: warp = half an image (49 two-patch items),
//    8192 warps total = single full-chip wave.
//  - item = 2 rows x 4 cols (two adjacent patches), two float4 loads, front-batched.
//  - item2 = item1+32: weight offset always +64 floats; pixel offset 2-way select.
//  - Horner form: dot(prefix-products, w) = c0*(w0 + c1*(w1 + c2*(w2 + c3*w3))).
//  - shfl butterfly reduce; even warps finalize their own image in parallel.

#define NPAIRS_HALF 49

// acc += <prefix-cos-products, (wa,wb)> for the two patches in one item (Horner)
__device__ __forceinline__ float item_contrib(float4 top, float4 bot,
                                              const float* __restrict__ wp,
                                              float acc)
{
    const float cA0 = __cosf(top.x), cA1 = __cosf(top.y);
    const float cA2 = __cosf(bot.x), cA3 = __cosf(bot.y);
    const float cB0 = __cosf(top.z), cB1 = __cosf(top.w);
    const float cB2 = __cosf(bot.z), cB3 = __cosf(bot.w);

    const float4 wa = __ldg(reinterpret_cast<const float4*>(wp));
    const float4 wb = __ldg(reinterpret_cast<const float4*>(wp + 4));

    const float hA = fmaf(cA1, fmaf(cA2, fmaf(cA3, wa.w, wa.z), wa.y), wa.x);
    acc = fmaf(cA0, hA, acc);
    const float hB = fmaf(cB1, fmaf(cB2, fmaf(cB3, wb.w, wb.z), wb.y), wb.x);
    acc = fmaf(cB0, hB, acc);
    return acc;
}

// final cos: Cody-Waite 2-term reduction + __cosf (|a| <~ 200), err ~1e-6
__device__ __forceinline__ float fast_cos_mid(float a)
{
    const float INV_2PI = 0.15915493667125702f;
    const float PI2_HI  = 6.28125f;
    const float PI2_LO  = 1.9353071795864769e-3f;
    const float k = rintf(a * INV_2PI);
    float r = fmaf(-k, PI2_HI, a);
    r = fmaf(-k, PI2_LO, r);
    return __cosf(r);
}

__global__ void __launch_bounds__(256, 8)
fraud_kernel(const float* __restrict__ x,   // [B, 784]
             const float* __restrict__ w,   // [785]
             float* __restrict__ out,       // [B]
             int B)
{
    const int tid  = threadIdx.x;
    const int warp = tid >> 5;
    const int lane = tid & 31;

    int b = blockIdx.x * 4 + (warp >> 1);
    if (b >= B) b = B - 1;                    // safe duplicate work; store is guarded
    const int half = warp & 1;

    const float* xb = x + (size_t)b * 784;

    // ---- item 1: p0 in [0,98) ----
    const int p0 = half * NPAIRS_HALF + lane;
    const int i0 = p0 / 7, c0 = p0 - i0 * 7;
    const float* q0 = xb + i0 * 56 + c0 * 4;
    const float4 t0 = __ldg(reinterpret_cast<const float4*>(q0));
    const float4 b0 = __ldg(reinterpret_cast<const float4*>(q0 + 28));

    // ---- item 2: p1 = p0 + 32 (lanes < 17 only) ----
    // weight offset: always +64 floats; pixel offset: +240 if c0<3 else +268
    const bool a1 = (lane < NPAIRS_HALF - 32);
    const float* q1 = q0 + ((c0 < 3) ? 240 : 268);
    float4 t1 = make_float4(0.f, 0.f, 0.f, 0.f), b1 = t1;
    if (a1) {
        t1 = __ldg(reinterpret_cast<const float4*>(q1));
        b1 = __ldg(reinterpret_cast<const float4*>(q1 + 28));
    }

    // ---- compute ----
    const float* wp0 = w + (i0 * 14 + 2 * c0) * 4;
    float acc = item_contrib(t0, b0, wp0, 0.0f);
    if (a1) acc = item_contrib(t1, b1, wp0 + 256, acc);

    // ---- warp butterfly reduce ----
    #pragma unroll
    for (int off = 16; off > 0; off >>= 1)
        acc += __shfl_xor_sync(0xffffffffu, acc, off);

    __shared__ float wsum[8];
    if (lane == 0) wsum[warp] = acc;
    __syncthreads();

    // each even warp finalizes its own image — parallel tails
    if (lane == 0 && (warp & 1) == 0) {
        const int img = blockIdx.x * 4 + (warp >> 1);
        if (img < B) {
            const float a  = wsum[warp] + wsum[warp + 1];
            const float cv = fast_cos_mid(a);
            out[img] = 1.0f / (1.0f + __expf(-cv));
        }
    }
}

extern "C" void kernel_launch(void* const* d_in, const int* in_sizes, int n_in,
                              void* d_out, int out_size)
{
    const float* x = (const float*)d_in[0];   // [B,1,28,28]
    // d_in[1] = patch_params — provably unused (RZ is pure phase)
    const float* w = (const float*)d_in[2];   // [785]
    float* out = (float*)d_out;

    const int B = in_sizes[0] / 784;
    const int grid = (B + 3) / 4;
    fraud_kernel<<<grid, 256>>>(x, w, out, B);
}